// round 14
// baseline (speedup 1.0000x reference)
#include <cuda_runtime.h>
#include <cuda_bf16.h>

#define B 512
#define D 768
#define MARGIN 1.0f
#define KSPLIT 8
#define KPER 96   // 768 / 8

// Scratch (allocation-free rule: __device__ globals)
__device__ float g_gramp[KSPLIT][B * B];  // K-split partial Gram planes, mirrored
__device__ float g_sqn[B];
__device__ double g_sum;
__device__ unsigned long long g_count;
__device__ unsigned int g_done;

// ---------------------------------------------------------------------------
// Kernel A: 296 blocks = 2 CTA/SM (16 warps/SM for latency hiding).
//   blocks 0..287  : upper-triangle Gram, 64x64 tiles, 4x4 micro-tile,
//                    K-split x8 (96 per block), pipelined loads, mirrored
//                    plane stores
//   blocks 288..295: sq-norms (64 rows each); block 295 resets scalars
// ---------------------------------------------------------------------------
__global__ void __launch_bounds__(256)
gram_sqnorm_kernel(const float* __restrict__ X) {
    __shared__ float As[16][68];  // [k][row], padded
    __shared__ float Bs[16][68];

    int bid = blockIdx.x;
    int tid = threadIdx.x;
    int lane = tid & 31, warp = tid >> 5;

    if (bid >= 288) {
        if (bid == 295 && tid == 0) {
            g_sum = 0.0;
            g_count = 0ull;
            g_done = 0u;
        }
        int rb = (bid - 288) * 64;
        #pragma unroll
        for (int i = 0; i < 8; i++) {
            int row = rb + warp * 8 + i;
            const float4* rp = (const float4*)(X + (size_t)row * D);
            float acc = 0.f;
            #pragma unroll
            for (int q = 0; q < 6; q++) {
                float4 v = rp[lane + 32 * q];
                acc += v.x * v.x + v.y * v.y + v.z * v.z + v.w * v.w;
            }
            #pragma unroll
            for (int o = 16; o; o >>= 1) acc += __shfl_down_sync(0xffffffffu, acc, o);
            if (lane == 0) g_sqn[row] = acc;
        }
        return;
    }

    int ks = bid & 7;            // k-slice 0..7
    int idx = bid >> 3, by = 0;  // tile 0..35 -> (by, bx), bx >= by, 8x8 grid
    for (;;) {
        int len = 8 - by;
        if (idx < len) break;
        idx -= len;
        by++;
    }
    int bx = by + idx;
    int rowBase = by * 64;
    int colBase = bx * 64;

    int tx = tid & 15, ty = tid >> 4;
    int lr = tid & 63;
    int lq = tid >> 6;

    const float* arow = X + (size_t)(rowBase + lr) * D + ks * KPER + lq * 4;
    const float* brow = X + (size_t)(colBase + lr) * D + ks * KPER + lq * 4;

    float acc[4][4];
    #pragma unroll
    for (int i = 0; i < 4; i++)
        #pragma unroll
        for (int j = 0; j < 4; j++) acc[i][j] = 0.f;

    float4 av = *(const float4*)arow;
    float4 bv = *(const float4*)brow;

    for (int kc = 0; kc < KPER; kc += 16) {
        As[lq * 4 + 0][lr] = av.x; As[lq * 4 + 1][lr] = av.y;
        As[lq * 4 + 2][lr] = av.z; As[lq * 4 + 3][lr] = av.w;
        Bs[lq * 4 + 0][lr] = bv.x; Bs[lq * 4 + 1][lr] = bv.y;
        Bs[lq * 4 + 2][lr] = bv.z; Bs[lq * 4 + 3][lr] = bv.w;
        __syncthreads();
        if (kc + 16 < KPER) {
            av = *(const float4*)(arow + kc + 16);
            bv = *(const float4*)(brow + kc + 16);
        }
        #pragma unroll
        for (int k = 0; k < 16; k++) {
            float4 a4 = *(const float4*)&As[k][ty * 4];
            float4 b4 = *(const float4*)&Bs[k][tx * 4];
            float a[4] = {a4.x, a4.y, a4.z, a4.w};
            float b[4] = {b4.x, b4.y, b4.z, b4.w};
            #pragma unroll
            for (int i = 0; i < 4; i++)
                #pragma unroll
                for (int j = 0; j < 4; j++) acc[i][j] += a[i] * b[j];
        }
        __syncthreads();
    }

    float* plane = g_gramp[ks];
    #pragma unroll
    for (int i = 0; i < 4; i++) {
        int r = rowBase + ty * 4 + i;
        *(float4*)&plane[r * B + colBase + tx * 4] =
            make_float4(acc[i][0], acc[i][1], acc[i][2], acc[i][3]);
    }
    if (bx != by) {
        #pragma unroll
        for (int j = 0; j < 4; j++) {
            int c = colBase + tx * 4 + j;
            *(float4*)&plane[c * B + rowBase + ty * 4] =
                make_float4(acc[0][j], acc[1][j], acc[2][j], acc[3][j]);
        }
    }
}

// ---------------------------------------------------------------------------
// Kernel B: one block per anchor. Hoisted wide-load prologue; ATOMIC-FREE
// compaction (warp w owns j in [64w, 64w+64); per-warp pos counts -> smem;
// offsets from an 8-element prefix); 4-positives-in-registers hinge loop.
// Last block finalizes.
// ---------------------------------------------------------------------------
__global__ void __launch_bounds__(256)
triplet_kernel(const int* __restrict__ types, float* __restrict__ out) {
    int a = blockIdx.x;
    __shared__ __align__(16) float posv[B + 4];
    __shared__ __align__(16) float negv[B + 4];
    __shared__ int wcnt[8];
    __shared__ float ws[8];
    int tid = threadIdx.x;
    int lane = tid & 31, warp = tid >> 5;

    // ---- hoisted loads: one MLP window ----
    float2 v0 = ((const float2*)&g_gramp[0][a * B])[tid];
    float2 v1 = ((const float2*)&g_gramp[1][a * B])[tid];
    float2 v2 = ((const float2*)&g_gramp[2][a * B])[tid];
    float2 v3 = ((const float2*)&g_gramp[3][a * B])[tid];
    float2 v4 = ((const float2*)&g_gramp[4][a * B])[tid];
    float2 v5 = ((const float2*)&g_gramp[5][a * B])[tid];
    float2 v6 = ((const float2*)&g_gramp[6][a * B])[tid];
    float2 v7 = ((const float2*)&g_gramp[7][a * B])[tid];
    float2 sq = ((const float2*)g_sqn)[tid];
    int2   tt = ((const int2*)types)[tid];
    int ta = types[a];
    float sa = g_sqn[a];

    int ja = 2 * tid, jb = 2 * tid + 1;
    float ga = ((v0.x + v1.x) + (v2.x + v3.x)) + ((v4.x + v5.x) + (v6.x + v7.x));
    float gb = ((v0.y + v1.y) + (v2.y + v3.y)) + ((v4.y + v5.y) + (v6.y + v7.y));
    float dva = (ja == a) ? 0.f : sqrtf(fmaxf(sa + sq.x - 2.f * ga, 0.f));
    float dvb = (jb == a) ? 0.f : sqrtf(fmaxf(sa + sq.y - 2.f * gb, 0.f));
    bool pa = (tt.x == ta);
    bool pb = (tt.y == ta);

    // ---- atomic-free compaction ----
    unsigned lt_mask = (1u << lane) - 1u;
    unsigned mpa = __ballot_sync(0xffffffffu, pa);
    unsigned mpb = __ballot_sync(0xffffffffu, pb);
    int cpa = __popc(mpa), cpb = __popc(mpb);
    if (lane == 0) wcnt[warp] = cpa + cpb;
    __syncthreads();

    int np = 0, base = 0;
    #pragma unroll
    for (int w = 0; w < 8; w++) {
        int c = wcnt[w];
        if (w < warp) base += c;
        np += c;
    }
    int nn = B - np;
    int nbase = warp * 64 - base;  // negatives before this warp

    if (pa) posv[base + __popc(mpa & lt_mask)] = dva;
    else    negv[nbase + __popc((~mpa) & lt_mask)] = dva;
    if (pb) posv[base + cpa + __popc(mpb & lt_mask)] = dvb;
    else    negv[nbase + (32 - cpa) + __popc((~mpb) & lt_mask)] = dvb;
    __syncthreads();

    int nn4 = (nn + 3) & ~3;
    int np4 = (np + 3) & ~3;
    if (tid < nn4 - nn) negv[nn + tid] = 1e30f;   // pad: max(dp - INF, 0) = 0
    if (tid < np4 - np) posv[np + tid] = -1e30f;  // pad: max(-INF - dn, 0) = 0
    __syncthreads();

    const float4* negv4 = (const float4*)negv;
    int nq = nn4 >> 2;
    float a0 = 0.f, a1 = 0.f, a2 = 0.f, a3 = 0.f;
    for (int p = warp * 4; p < np4; p += 32) {  // 8 warps x 4 positives each
        float dp0 = posv[p + 0] + MARGIN;
        float dp1 = posv[p + 1] + MARGIN;
        float dp2 = posv[p + 2] + MARGIN;
        float dp3 = posv[p + 3] + MARGIN;
        for (int n = lane; n < nq; n += 32) {
            float4 v = negv4[n];
            a0 += fmaxf(dp0 - v.x, 0.f); a0 += fmaxf(dp0 - v.y, 0.f);
            a0 += fmaxf(dp0 - v.z, 0.f); a0 += fmaxf(dp0 - v.w, 0.f);
            a1 += fmaxf(dp1 - v.x, 0.f); a1 += fmaxf(dp1 - v.y, 0.f);
            a1 += fmaxf(dp1 - v.z, 0.f); a1 += fmaxf(dp1 - v.w, 0.f);
            a2 += fmaxf(dp2 - v.x, 0.f); a2 += fmaxf(dp2 - v.y, 0.f);
            a2 += fmaxf(dp2 - v.z, 0.f); a2 += fmaxf(dp2 - v.w, 0.f);
            a3 += fmaxf(dp3 - v.x, 0.f); a3 += fmaxf(dp3 - v.y, 0.f);
            a3 += fmaxf(dp3 - v.z, 0.f); a3 += fmaxf(dp3 - v.w, 0.f);
        }
    }
    float acc = (a0 + a1) + (a2 + a3);

    #pragma unroll
    for (int o = 16; o; o >>= 1) acc += __shfl_down_sync(0xffffffffu, acc, o);
    if (lane == 0) ws[warp] = acc;
    __syncthreads();
    if (tid == 0) {
        float s = 0.f;
        #pragma unroll
        for (int w = 0; w < 8; w++) s += ws[w];
        atomicAdd(&g_sum, (double)s);
        atomicAdd(&g_count, (unsigned long long)((long long)np * nn));
        __threadfence();
        unsigned d = atomicInc(&g_done, 0xffffffffu);
        if (d == B - 1) {
            double S = atomicAdd(&g_sum, 0.0);
            unsigned long long C = atomicAdd(&g_count, 0ull);
            double V = (double)C;
            double b3 = 134217728.0;  // 512^3
            out[0] = (float)(((b3 - V) * (double)MARGIN + S) / V);
        }
    }
}

extern "C" void kernel_launch(void* const* d_in, const int* in_sizes, int n_in,
                              void* d_out, int out_size) {
    int ti = 0, ei = 1;
    if (in_sizes[0] == B * D) { ti = 1; ei = 0; }
    const int* types = (const int*)d_in[ti];
    const float* X = (const float*)d_in[ei];
    float* out = (float*)d_out;

    gram_sqnorm_kernel<<<296, 256>>>(X);
    triplet_kernel<<<B, 256>>>(types, out);
}